// round 13
// baseline (speedup 1.0000x reference)
#include <cuda_runtime.h>
#include <cstdint>

// ThresholdDecision: out[b] = 1.0f iff exists t in [1, L-CP-1] with
// x[b, t..t+CP-1, 2] > 0.5 (CP=4), else 0.0f. fp32 in, fp32 out.
//
// R12: traffic is cheap now (~5-6 MB vs 201 MB full scan); the cost is
// SERIALIZED DRAM round trips. So speculate: load 128 positions in ONE
// batch (4 independent ballot words -> single round trip) before any
// ballot. P(miss 128) = e^-4 -> only ~74/4096 rows take a second trip
// (+288, cum 416); P(miss 416) = e^-13 -> fallback population ~0.009 rows,
// i.e. never in practice. Critical path = 1 big round trip + 1 latency-only
// straggler trip. Expected traffic ~6.3 MB.

#define WARPS_PER_BLOCK 8
#define NTHREADS (WARPS_PER_BLOCK * 32)

// Scan W ballot-words (W*32 positions) starting at `base`. carry holds the
// top 3 bits of the previous word's bit-stream. Returns warp-uniform flag.
template <int W>
__device__ __forceinline__ int scan_words(const float* __restrict__ xr,
                                          int base, int L, int lane,
                                          unsigned int& carry)
{
    float v[W];
    #pragma unroll
    for (int j = 0; j < W; ++j) {
        const int p = base + j * 32 + lane;
        v[j] = (p < L) ? __ldg(&xr[(size_t)p * 3 + 2]) : 0.0f;
    }

    int found = 0;
    #pragma unroll
    for (int j = 0; j < W; ++j) {
        const int p = base + j * 32 + lane;
        // positions 0 and L-1 excluded (window t >= 1, t+3 <= L-2)
        const int pred = (v[j] > 0.5f) & (p >= 1) & (p <= L - 2);
        const unsigned int w = __ballot_sync(0xffffffffu, pred);
        const unsigned long long t = ((unsigned long long)w << 3) | carry;
        const unsigned long long r = t & (t >> 1) & (t >> 2) & (t >> 3);
        found |= (r != 0ull);
        carry = w >> 29;
    }
    return found;
}

__global__ void __launch_bounds__(NTHREADS)
threshold_decision_kernel(const float* __restrict__ x,
                          float* __restrict__ out,
                          int L, int B)
{
    const int lane = threadIdx.x & 31;
    const int warp = threadIdx.x >> 5;
    const int row  = blockIdx.x * WARPS_PER_BLOCK + warp;
    if (row >= B) return;

    const float* __restrict__ xr = x + (size_t)row * (size_t)L * 3u;

    unsigned int carry = 0u;

    // Phase A: 128 positions, all loads issued before any ballot ->
    // exactly one DRAM round trip. 98.2% of rows finish here.
    int found = scan_words<4>(xr, 0, L, lane, carry);

    // Phase B: +288 positions (cum 416) for the ~74 straggler rows.
    if (!found && L > 128)
        found = scan_words<9>(xr, 128, L, lane, carry);

    // Fallback: exhaustive 1024-position chunks (correctness guarantee on
    // adversarial data; population ~e^-13 per row on this dataset).
    for (int base = 416; !found && base < L; base += 1024)
        found = scan_words<32>(xr, base, L, lane, carry);

    if (lane == 0) out[row] = found ? 1.0f : 0.0f;
}

extern "C" void kernel_launch(void* const* d_in, const int* in_sizes, int n_in,
                              void* d_out, int out_size)
{
    const int B = out_size;   // one flag per row

    // Select the input whose element count is divisible by B*3.
    const float* x = (const float*)d_in[0];
    long long total = in_sizes[0];
    for (int i = 0; i < n_in; ++i) {
        long long s = in_sizes[i];
        if (s >= (long long)B * 3 && s % ((long long)B * 3) == 0) {
            x = (const float*)d_in[i];
            total = s;
            break;
        }
    }
    const int L = (int)(total / ((long long)B * 3));

    const int grid = (B + WARPS_PER_BLOCK - 1) / WARPS_PER_BLOCK;
    threshold_decision_kernel<<<grid, NTHREADS>>>(x, (float*)d_out, L, B);
}